// round 1
// baseline (speedup 1.0000x reference)
#include <cuda_runtime.h>

#define NB 16
#define LL 1024
#define DH 256
#define NEGINF (-1e30f)
#define FLT_LOW (-3.4e38f)

// ---------------- scratch (static device globals; no allocation) -------------
__device__ float g_PW[NB * LL * DH];        // 16 MB   P @ W
__device__ float g_sim[NB * LL * LL];       // 67 MB   bilinear scores (+bias,+mask)
__device__ float g_rowmax[NB * LL];
__device__ float g_rowinv[NB * LL];
__device__ float g_colpart[NB * 8 * LL];    // partial column maxes (8 p-chunks)
__device__ float g_pvec[NB * DH];           // aligned premise vector per batch

// =============================================================================
// Kernel A: g_PW = P(16384x256) @ W(256x256)   (NN)
// 128x128x8 tile, 256 threads, 8x8 per thread
// =============================================================================
__global__ __launch_bounds__(256, 2) void k_pw(const float* __restrict__ P,
                                               const float* __restrict__ W) {
    __shared__ float As[8][128];
    __shared__ float Bs[8][128];
    const int tid = threadIdx.x;
    const int tx = tid & 15, ty = tid >> 4;
    const int bn = blockIdx.x * 128;
    const int bm = blockIdx.y * 128;
    const int aRow = tid >> 1, aCol = (tid & 1) * 4;
    const int bRow = tid >> 5, bCol = (tid & 31) * 4;
    const float* Ap = P + (size_t)(bm + aRow) * DH + aCol;
    const float* Bp = W + (size_t)bRow * DH + bn + bCol;

    float acc[8][8];
#pragma unroll
    for (int i = 0; i < 8; i++)
#pragma unroll
        for (int j = 0; j < 8; j++) acc[i][j] = 0.0f;

    for (int k0 = 0; k0 < DH; k0 += 8) {
        float4 av = *(const float4*)(Ap + k0);
        float4 bv = *(const float4*)(Bp + (size_t)k0 * DH);
        As[aCol + 0][aRow] = av.x; As[aCol + 1][aRow] = av.y;
        As[aCol + 2][aRow] = av.z; As[aCol + 3][aRow] = av.w;
        *(float4*)&Bs[bRow][bCol] = bv;
        __syncthreads();
#pragma unroll
        for (int kk = 0; kk < 8; kk++) {
            float4 a0 = *(const float4*)&As[kk][ty * 8];
            float4 a1 = *(const float4*)&As[kk][ty * 8 + 4];
            float4 b0 = *(const float4*)&Bs[kk][tx * 8];
            float4 b1 = *(const float4*)&Bs[kk][tx * 8 + 4];
            float ra[8] = {a0.x, a0.y, a0.z, a0.w, a1.x, a1.y, a1.z, a1.w};
            float rb[8] = {b0.x, b0.y, b0.z, b0.w, b1.x, b1.y, b1.z, b1.w};
#pragma unroll
            for (int i = 0; i < 8; i++)
#pragma unroll
                for (int j = 0; j < 8; j++)
                    acc[i][j] = fmaf(ra[i], rb[j], acc[i][j]);
        }
        __syncthreads();
    }
#pragma unroll
    for (int i = 0; i < 8; i++) {
        int gm = bm + ty * 8 + i;
        float* o = g_PW + (size_t)gm * DH + bn + tx * 8;
        *(float4*)(o)     = make_float4(acc[i][0], acc[i][1], acc[i][2], acc[i][3]);
        *(float4*)(o + 4) = make_float4(acc[i][4], acc[i][5], acc[i][6], acc[i][7]);
    }
}

// =============================================================================
// Kernel B: g_sim[b] = g_PW[b] @ H[b]^T + bias + mask   (NT, per batch)
// =============================================================================
__global__ __launch_bounds__(256, 2) void k_sim(const float* __restrict__ Hh,
                                                const int* __restrict__ pmask,
                                                const int* __restrict__ hmask,
                                                const float* __restrict__ bias) {
    __shared__ float As[8][128];
    __shared__ float Bs[8][128];
    const int b = blockIdx.z;
    const int tid = threadIdx.x;
    const int tx = tid & 15, ty = tid >> 4;
    const int bn = blockIdx.x * 128;
    const int bm = blockIdx.y * 128;
    const int r = tid >> 1, c4 = (tid & 1) * 4;
    const float* Ap = g_PW + (size_t)b * LL * DH + (size_t)(bm + r) * DH + c4;
    const float* Bp = Hh   + (size_t)b * LL * DH + (size_t)(bn + r) * DH + c4;

    float acc[8][8];
#pragma unroll
    for (int i = 0; i < 8; i++)
#pragma unroll
        for (int j = 0; j < 8; j++) acc[i][j] = 0.0f;

    for (int k0 = 0; k0 < DH; k0 += 8) {
        float4 av = *(const float4*)(Ap + k0);
        float4 bv = *(const float4*)(Bp + k0);
        As[c4 + 0][r] = av.x; As[c4 + 1][r] = av.y;
        As[c4 + 2][r] = av.z; As[c4 + 3][r] = av.w;
        Bs[c4 + 0][r] = bv.x; Bs[c4 + 1][r] = bv.y;
        Bs[c4 + 2][r] = bv.z; Bs[c4 + 3][r] = bv.w;
        __syncthreads();
#pragma unroll
        for (int kk = 0; kk < 8; kk++) {
            float4 a0 = *(const float4*)&As[kk][ty * 8];
            float4 a1 = *(const float4*)&As[kk][ty * 8 + 4];
            float4 b0 = *(const float4*)&Bs[kk][tx * 8];
            float4 b1 = *(const float4*)&Bs[kk][tx * 8 + 4];
            float ra[8] = {a0.x, a0.y, a0.z, a0.w, a1.x, a1.y, a1.z, a1.w};
            float rb[8] = {b0.x, b0.y, b0.z, b0.w, b1.x, b1.y, b1.z, b1.w};
#pragma unroll
            for (int i = 0; i < 8; i++)
#pragma unroll
                for (int j = 0; j < 8; j++)
                    acc[i][j] = fmaf(ra[i], rb[j], acc[i][j]);
        }
        __syncthreads();
    }

    const float bb = bias[0];
    float pmv[8], hmv[8];
#pragma unroll
    for (int i = 0; i < 8; i++) pmv[i] = (float)pmask[b * LL + bm + ty * 8 + i];
#pragma unroll
    for (int j = 0; j < 8; j++) hmv[j] = (float)hmask[b * LL + bn + tx * 8 + j];

#pragma unroll
    for (int i = 0; i < 8; i++) {
        int gm = bm + ty * 8 + i;
        float v[8];
#pragma unroll
        for (int j = 0; j < 8; j++)
            v[j] = acc[i][j] + bb + (1.0f - pmv[i] * hmv[j]) * NEGINF;
        float* o = g_sim + ((size_t)b * LL + gm) * LL + bn + tx * 8;
        *(float4*)(o)     = make_float4(v[0], v[1], v[2], v[3]);
        *(float4*)(o + 4) = make_float4(v[4], v[5], v[6], v[7]);
    }
}

// =============================================================================
// Kernel C: per-row max & 1/sum(exp)  (one block of 128 threads per row)
// =============================================================================
__global__ void k_rowstats() {
    const int row = blockIdx.x;             // b*LL + p
    const float* s = g_sim + (size_t)row * LL;
    const int t = threadIdx.x;
    float4 v0 = *(const float4*)(s + t * 8);
    float4 v1 = *(const float4*)(s + t * 8 + 4);
    float m = fmaxf(fmaxf(fmaxf(v0.x, v0.y), fmaxf(v0.z, v0.w)),
                    fmaxf(fmaxf(v1.x, v1.y), fmaxf(v1.z, v1.w)));
#pragma unroll
    for (int o = 16; o > 0; o >>= 1) m = fmaxf(m, __shfl_xor_sync(0xffffffffu, m, o));
    __shared__ float sm[4], ss[4];
    const int w = t >> 5, lane = t & 31;
    if (lane == 0) sm[w] = m;
    __syncthreads();
    m = fmaxf(fmaxf(sm[0], sm[1]), fmaxf(sm[2], sm[3]));
    float sum = __expf(v0.x - m) + __expf(v0.y - m) + __expf(v0.z - m) + __expf(v0.w - m)
              + __expf(v1.x - m) + __expf(v1.y - m) + __expf(v1.z - m) + __expf(v1.w - m);
#pragma unroll
    for (int o = 16; o > 0; o >>= 1) sum += __shfl_xor_sync(0xffffffffu, sum, o);
    if (lane == 0) ss[w] = sum;
    __syncthreads();
    if (t == 0) {
        g_rowmax[row] = m;
        g_rowinv[row] = 1.0f / (ss[0] + ss[1] + ss[2] + ss[3]);
    }
}

// =============================================================================
// Kernel C2: partial column maxes (grid: qchunk=4, pchunk=8, batch)
// =============================================================================
__global__ void k_colmax() {
    const int b = blockIdx.z;
    const int q = blockIdx.x * 256 + threadIdx.x;
    const int p0 = blockIdx.y * 128;
    const float* s = g_sim + ((size_t)b * LL + p0) * LL + q;
    float m = FLT_LOW;
#pragma unroll 8
    for (int p = 0; p < 128; p++) m = fmaxf(m, s[(size_t)p * LL]);
    g_colpart[((size_t)b * 8 + blockIdx.y) * LL + q] = m;
}

// =============================================================================
// Kernel D: aligned_hyp[b] = softmax(sim[b]) @ H[b]   (NN, on-the-fly probs)
// =============================================================================
__global__ __launch_bounds__(256, 2) void k_av(const float* __restrict__ Hh,
                                               float* __restrict__ out) {
    __shared__ float As[8][128];
    __shared__ float Bs[8][128];
    const int b = blockIdx.z;
    const int tid = threadIdx.x;
    const int tx = tid & 15, ty = tid >> 4;
    const int bn = blockIdx.x * 128;     // over DH (2 tiles)
    const int bm = blockIdx.y * 128;     // over rows
    const int aRow = tid >> 1, aCol = (tid & 1) * 4;
    const int bRow = tid >> 5, bCol = (tid & 31) * 4;
    const int grow = bm + aRow;
    const float rm = g_rowmax[b * LL + grow];
    const float ri = g_rowinv[b * LL + grow];
    const float* Ap = g_sim + ((size_t)b * LL + grow) * LL + aCol;
    const float* Bp = Hh + (size_t)b * LL * DH + (size_t)bRow * DH + bn + bCol;

    float acc[8][8];
#pragma unroll
    for (int i = 0; i < 8; i++)
#pragma unroll
        for (int j = 0; j < 8; j++) acc[i][j] = 0.0f;

    for (int k0 = 0; k0 < LL; k0 += 8) {
        float4 av = *(const float4*)(Ap + k0);
        av.x = __expf(av.x - rm) * ri;
        av.y = __expf(av.y - rm) * ri;
        av.z = __expf(av.z - rm) * ri;
        av.w = __expf(av.w - rm) * ri;
        float4 bv = *(const float4*)(Bp + (size_t)k0 * DH);
        As[aCol + 0][aRow] = av.x; As[aCol + 1][aRow] = av.y;
        As[aCol + 2][aRow] = av.z; As[aCol + 3][aRow] = av.w;
        *(float4*)&Bs[bRow][bCol] = bv;
        __syncthreads();
#pragma unroll
        for (int kk = 0; kk < 8; kk++) {
            float4 a0 = *(const float4*)&As[kk][ty * 8];
            float4 a1 = *(const float4*)&As[kk][ty * 8 + 4];
            float4 b0 = *(const float4*)&Bs[kk][tx * 8];
            float4 b1 = *(const float4*)&Bs[kk][tx * 8 + 4];
            float ra[8] = {a0.x, a0.y, a0.z, a0.w, a1.x, a1.y, a1.z, a1.w};
            float rb[8] = {b0.x, b0.y, b0.z, b0.w, b1.x, b1.y, b1.z, b1.w};
#pragma unroll
            for (int i = 0; i < 8; i++)
#pragma unroll
                for (int j = 0; j < 8; j++)
                    acc[i][j] = fmaf(ra[i], rb[j], acc[i][j]);
        }
        __syncthreads();
    }
#pragma unroll
    for (int i = 0; i < 8; i++) {
        int gm = bm + ty * 8 + i;
        float* o = out + (size_t)b * LL * DH + (size_t)gm * DH + bn + tx * 8;
        *(float4*)(o)     = make_float4(acc[i][0], acc[i][1], acc[i][2], acc[i][3]);
        *(float4*)(o + 4) = make_float4(acc[i][4], acc[i][5], acc[i][6], acc[i][7]);
    }
}

// =============================================================================
// Kernel E: per batch — softmax(colmax) @ P -> g_pvec[b, 256]
// =============================================================================
__global__ __launch_bounds__(256) void k_premise(const float* __restrict__ P) {
    const int b = blockIdx.x;
    const int t = threadIdx.x;
    __shared__ float prob[LL];
    __shared__ float red[8];
    float loc[4];
#pragma unroll
    for (int c = 0; c < 4; c++) {
        int q = c * 256 + t;
        float m = FLT_LOW;
#pragma unroll
        for (int j = 0; j < 8; j++)
            m = fmaxf(m, g_colpart[((size_t)b * 8 + j) * LL + q]);
        loc[c] = m;
    }
    float mx = fmaxf(fmaxf(loc[0], loc[1]), fmaxf(loc[2], loc[3]));
#pragma unroll
    for (int o = 16; o > 0; o >>= 1) mx = fmaxf(mx, __shfl_xor_sync(0xffffffffu, mx, o));
    const int w = t >> 5, lane = t & 31;
    if (lane == 0) red[w] = mx;
    __syncthreads();
    mx = red[0];
#pragma unroll
    for (int j = 1; j < 8; j++) mx = fmaxf(mx, red[j]);

    float se = 0.0f;
#pragma unroll
    for (int c = 0; c < 4; c++) {
        float e = __expf(loc[c] - mx);
        prob[c * 256 + t] = e;
        se += e;
    }
#pragma unroll
    for (int o = 16; o > 0; o >>= 1) se += __shfl_xor_sync(0xffffffffu, se, o);
    __syncthreads();               // red reads done before reuse
    if (lane == 0) red[w] = se;
    __syncthreads();
    float tot = 0.0f;
#pragma unroll
    for (int j = 0; j < 8; j++) tot += red[j];
    const float inv = 1.0f / tot;

    const float* Pb = P + (size_t)b * LL * DH + t;   // thread t owns dim d=t
    float acc = 0.0f;
#pragma unroll 8
    for (int q = 0; q < LL; q++)
        acc = fmaf(prob[q], Pb[(size_t)q * DH], acc);
    g_pvec[b * DH + t] = acc * inv;
}

// =============================================================================
// Kernel F: broadcast g_pvec -> out[0 : NB*LL*DH)
// =============================================================================
__global__ void k_bcast(float* __restrict__ out) {
    int idx = (blockIdx.x * 256 + threadIdx.x) * 4;   // < 4194304
    int b = idx >> 18;           // LL*DH = 2^18
    int d = idx & (DH - 1);
    float4 v = *(const float4*)&g_pvec[b * DH + d];
    *(float4*)&out[idx] = v;
}

// =============================================================================
extern "C" void kernel_launch(void* const* d_in, const int* in_sizes, int n_in,
                              void* d_out, int out_size) {
    const float* P    = (const float*)d_in[0];
    const float* Hh   = (const float*)d_in[1];
    const int*   pm   = (const int*)d_in[2];
    const int*   hm   = (const int*)d_in[3];
    const float* W    = (const float*)d_in[4];
    const float* bias = (const float*)d_in[5];
    float* out = (float*)d_out;

    k_pw      <<<dim3(DH / 128, (NB * LL) / 128), 256>>>(P, W);
    k_sim     <<<dim3(LL / 128, LL / 128, NB), 256>>>(Hh, pm, hm, bias);
    k_rowstats<<<NB * LL, 128>>>();
    k_colmax  <<<dim3(LL / 256, 8, NB), 256>>>();
    k_av      <<<dim3(DH / 128, LL / 128, NB), 256>>>(Hh, out + (size_t)NB * LL * DH);
    k_premise <<<NB, 256>>>(P);
    k_bcast   <<<(NB * LL * DH) / (256 * 4), 256>>>(out);
}